// round 7
// baseline (speedup 1.0000x reference)
#include <cuda_runtime.h>
#include <cstdint>

// ---------------------------------------------------------------------------
// Problem constants
// ---------------------------------------------------------------------------
#define NROWS 32768            // 64*512
#define KC    1024             // num centers
#define DDIM  256              // latent dim
#define BM    128              // CTA rows; CTA owns ALL 1024 output cols
#define BN    128              // column block per GEMM pass
#define NCB   (KC / BN)        // 8 column blocks
#define NJ    (NCB * 8)        // 64 flat (cb,k) iterations (K-chunk 32)
#define NSTG  4                // cp.async pipeline stages

#define A_STAGE 16384          // 128 x 32 f32
#define B_STAGE 16384
#define SMEM_SZ (NSTG * (A_STAGE + B_STAGE))   // 131072

// ---------------------------------------------------------------------------
// Device-global scratch
// ---------------------------------------------------------------------------
__device__ float g_zsq[NROWS];
__device__ float g_csq[KC];

// ---------------------------------------------------------------------------
// helpers (sm_80-era PTX only — plain sm_100 target)
// ---------------------------------------------------------------------------
__device__ __forceinline__ uint32_t smem_u32(const void* p) {
    uint32_t a;
    asm("{ .reg .u64 t; cvta.to.shared.u64 t, %1; cvt.u32.u64 %0, t; }"
        : "=r"(a) : "l"(p));
    return a;
}
__device__ __forceinline__ void cpasync16(uint32_t dst, const void* src) {
    asm volatile("cp.async.cg.shared.global [%0], [%1], 16;"
                 :: "r"(dst), "l"(src));
}
__device__ __forceinline__ void ldsm4(uint32_t addr, uint32_t* d) {
    asm volatile("ldmatrix.sync.aligned.m8n8.x4.shared.b16 {%0,%1,%2,%3}, [%4];"
                 : "=r"(d[0]), "=r"(d[1]), "=r"(d[2]), "=r"(d[3])
                 : "r"(addr));
}
__device__ __forceinline__ void mma_tf32(float* c, const uint32_t* a,
                                         uint32_t b0, uint32_t b1) {
    asm volatile(
        "mma.sync.aligned.m16n8k8.row.col.f32.tf32.tf32.f32 "
        "{%0,%1,%2,%3}, {%4,%5,%6,%7}, {%8,%9}, {%0,%1,%2,%3};"
        : "+f"(c[0]), "+f"(c[1]), "+f"(c[2]), "+f"(c[3])
        : "r"(a[0]), "r"(a[1]), "r"(a[2]), "r"(a[3]), "r"(b0), "r"(b1));
}

// ---------------------------------------------------------------------------
// Kernel 1: prep — squared row norms
// ---------------------------------------------------------------------------
__global__ void prep_kernel(const float* __restrict__ z,
                            const float* __restrict__ c) {
    int gw   = (blockIdx.x * blockDim.x + threadIdx.x) >> 5;
    int lane = threadIdx.x & 31;
    if (gw >= NROWS + KC) return;
    const float4* s4 = (gw < NROWS)
        ? (const float4*)(z + (size_t)gw * DDIM)
        : (const float4*)(c + (size_t)(gw - NROWS) * DDIM);
    float4 a = s4[lane], b = s4[lane + 32];
    float s = a.x * a.x + a.y * a.y + a.z * a.z + a.w * a.w
            + b.x * b.x + b.y * b.y + b.z * b.z + b.w * b.w;
    #pragma unroll
    for (int o = 16; o > 0; o >>= 1) s += __shfl_down_sync(0xffffffffu, s, o);
    if (lane == 0) {
        if (gw < NROWS) g_zsq[gw] = s;
        else            g_csq[gw - NROWS] = s;
    }
}

// ---------------------------------------------------------------------------
// Kernel 2: full-row fused GEMM + Student-t + in-CTA normalization
// grid = 256 CTAs, 512 threads (16 warps: 4M x 4N), warp tile 32x32
// 4-stage cp.async pipeline, single barrier per K-chunk
// ---------------------------------------------------------------------------
__global__ void __launch_bounds__(512, 1)
gemm_kernel(const float* __restrict__ z, const float* __restrict__ cen,
            float* __restrict__ out) {
    extern __shared__ __align__(16) char smem[];
    uint32_t sb = smem_u32(smem);
    const uint32_t A0 = sb;
    const uint32_t B0 = sb + NSTG * A_STAGE;

    int tid  = threadIdx.x;
    int wid  = tid >> 5;
    int lane = tid & 31;
    int gr0  = blockIdx.x * BM;
    int wm   = (wid & 3) * 32;          // warp M offset (4 warps along M)
    int wn   = (wid >> 2) * 32;         // warp N offset (4 warps along N)
    int wnid = wid >> 2;

    // ---- chunk loader: j -> (cb = j>>3, k = j&7), stage j&3 ----
    auto load_chunk = [&](int j) {
        int cb = j >> 3, k = j & 7;
        uint32_t ab = A0 + (j & 3) * A_STAGE;
        uint32_t bb = B0 + (j & 3) * B_STAGE;
        const float* gA = z   + (size_t)gr0 * DDIM + k * 32;
        const float* gB = cen + (size_t)(cb * BN) * DDIM + k * 32;
        #pragma unroll
        for (int u = 0; u < 2; u++) {            // 1024 float4 / 512 threads
            int f = u * 512 + tid;
            int row = f >> 3, c4 = f & 7;
            cpasync16(ab + row * 128 + 16 * (c4 ^ (row & 7)),
                      gA + (size_t)row * DDIM + c4 * 4);
        }
        #pragma unroll
        for (int u = 0; u < 2; u++) {
            int f = u * 512 + tid;
            int row = f >> 3, c4 = f & 7;
            cpasync16(bb + row * 128 + 16 * (c4 ^ (row & 7)),
                      gB + (size_t)row * DDIM + c4 * 4);
        }
        asm volatile("cp.async.commit_group;");
    };
    load_chunk(0);
    load_chunk(1);
    load_chunk(2);

    // ---- ldmatrix address precompute ----
    int g = lane >> 3, r = lane & 7;
    uint32_t aOff[2], aSw[2];
    #pragma unroll
    for (int ms = 0; ms < 2; ms++) {
        int row = wm + ms * 16 + (g & 1) * 8 + r;
        aOff[ms] = (uint32_t)row * 128;
        aSw[ms]  = (uint32_t)(row & 7);
    }
    uint32_t aDu = (uint32_t)(g >> 1);
    uint32_t bOff[2], bSw[2];
    #pragma unroll
    for (int nj = 0; nj < 2; nj++) {
        int row = wn + nj * 16 + (g >> 1) * 8 + r;
        bOff[nj] = (uint32_t)row * 128;
        bSw[nj]  = (uint32_t)(row & 7);
    }
    uint32_t bDu = (uint32_t)(g & 1);

    float acc[2][4][4];
    #pragma unroll
    for (int ms = 0; ms < 2; ms++)
        #pragma unroll
        for (int ns = 0; ns < 4; ns++)
            #pragma unroll
            for (int q = 0; q < 4; q++) acc[ms][ns][q] = 0.0f;

    int tig = lane & 3, gid = lane >> 2;
    float rs[2][2] = {{0.f, 0.f}, {0.f, 0.f}};

    // ---- flat mainloop: single barrier per chunk, 4-stage prefetch ----
    #pragma unroll 1
    for (int j = 0; j < NJ; j++) {
        asm volatile("cp.async.wait_group 2;");   // group j retired
        __syncthreads();

        // refill stage (j+3)&3 == (j-1)&3 (its compute finished pre-barrier)
        if (j + 3 < NJ) load_chunk(j + 3);
        else            asm volatile("cp.async.commit_group;");  // keep count

        uint32_t ab = A0 + (j & 3) * A_STAGE;
        uint32_t bb = B0 + (j & 3) * B_STAGE;
        #pragma unroll
        for (int kk = 0; kk < 4; kk++) {
            uint32_t afr[2][4], bfr[2][4];
            #pragma unroll
            for (int ms = 0; ms < 2; ms++)
                ldsm4(ab + aOff[ms] + 16 * ((2 * kk + aDu) ^ aSw[ms]), afr[ms]);
            #pragma unroll
            for (int nj = 0; nj < 2; nj++)
                ldsm4(bb + bOff[nj] + 16 * ((2 * kk + bDu) ^ bSw[nj]), bfr[nj]);
            #pragma unroll
            for (int ms = 0; ms < 2; ms++)
                #pragma unroll
                for (int ns = 0; ns < 4; ns++)
                    mma_tf32(acc[ms][ns], afr[ms],
                             bfr[ns >> 1][(ns & 1) * 2],
                             bfr[ns >> 1][(ns & 1) * 2 + 1]);
        }

        if ((j & 7) == 7) {
            // ---- epilogue for finished column block (overlaps prefetch) ----
            int cb = j >> 3;
            #pragma unroll
            for (int ms = 0; ms < 2; ms++) {
                int r0 = gr0 + wm + 16 * ms + gid;
                float zs0 = g_zsq[r0];
                float zs1 = g_zsq[r0 + 8];
                #pragma unroll
                for (int ns = 0; ns < 4; ns++) {
                    int col = cb * BN + wn + 8 * ns + 2 * tig;
                    float cs0 = __ldg(&g_csq[col]);
                    float cs1 = __ldg(&g_csq[col + 1]);
                    float d00 = fmaxf(fmaf(-2.0f, acc[ms][ns][0], zs0 + cs0), 0.0f);
                    float d01 = fmaxf(fmaf(-2.0f, acc[ms][ns][1], zs0 + cs1), 0.0f);
                    float d10 = fmaxf(fmaf(-2.0f, acc[ms][ns][2], zs1 + cs0), 0.0f);
                    float d11 = fmaxf(fmaf(-2.0f, acc[ms][ns][3], zs1 + cs1), 0.0f);
                    float s00, s01, s10, s11;
                    { float x = fmaf(d00, 0.1f, 1.0f); float y = rsqrtf(x);
                      float y2 = y*y, y4 = y2*y2, y8 = y4*y4; s00 = y8*y2*y; }
                    { float x = fmaf(d01, 0.1f, 1.0f); float y = rsqrtf(x);
                      float y2 = y*y, y4 = y2*y2, y8 = y4*y4; s01 = y8*y2*y; }
                    { float x = fmaf(d10, 0.1f, 1.0f); float y = rsqrtf(x);
                      float y2 = y*y, y4 = y2*y2, y8 = y4*y4; s10 = y8*y2*y; }
                    { float x = fmaf(d11, 0.1f, 1.0f); float y = rsqrtf(x);
                      float y2 = y*y, y4 = y2*y2, y8 = y4*y4; s11 = y8*y2*y; }
                    rs[ms][0] += s00 + s01;
                    rs[ms][1] += s10 + s11;
                    *(float2*)(out + (size_t)r0 * KC + col)       = make_float2(s00, s01);
                    *(float2*)(out + (size_t)(r0 + 8) * KC + col) = make_float2(s10, s11);
                    acc[ms][ns][0] = 0.f; acc[ms][ns][1] = 0.f;
                    acc[ms][ns][2] = 0.f; acc[ms][ns][3] = 0.f;
                }
            }
        }
    }

    // ---- row-sum reduction: quad -> smem -> inv per row ----
    #pragma unroll
    for (int ms = 0; ms < 2; ms++)
        #pragma unroll
        for (int h = 0; h < 2; h++) {
            float v = rs[ms][h];
            v += __shfl_xor_sync(0xffffffffu, v, 1);
            v += __shfl_xor_sync(0xffffffffu, v, 2);
            rs[ms][h] = v;
        }
    __syncthreads();                  // tiles dead; reuse smem
    float* red = (float*)smem;        // [128 rows][4 warp_n]
    float* inv = red + 512;
    if (tig == 0) {
        #pragma unroll
        for (int ms = 0; ms < 2; ms++)
            #pragma unroll
            for (int h = 0; h < 2; h++)
                red[(wm + 16 * ms + 8 * h + gid) * 4 + wnid] = rs[ms][h];
    }
    __syncthreads();
    if (tid < BM)
        inv[tid] = 1.0f / (red[tid * 4] + red[tid * 4 + 1]
                         + red[tid * 4 + 2] + red[tid * 4 + 3]);
    __syncthreads();

    // ---- in-CTA normalization pass over own 512KB tile (L2-hot) ----
    float4* o4 = (float4*)out + (size_t)gr0 * (KC / 4);
    #pragma unroll 4
    for (int u = 0; u < 64; u++) {
        int idx = u * 512 + tid;
        float iv = inv[idx >> 8];          // 256 float4 per row
        float4 v = o4[idx];
        v.x *= iv; v.y *= iv; v.z *= iv; v.w *= iv;
        o4[idx] = v;
    }
}

// ---------------------------------------------------------------------------
extern "C" void kernel_launch(void* const* d_in, const int* in_sizes, int n_in,
                              void* d_out, int out_size) {
    const float* z = (const float*)d_in[0];
    const float* c = (const float*)d_in[1];
    if (in_sizes[0] == KC * DDIM) {          // defensive: metadata order
        const float* t = z; z = c; c = t;
    }
    float* out = (float*)d_out;

    static int smem_set = 0;
    if (!smem_set) {
        cudaFuncSetAttribute(gemm_kernel,
                             cudaFuncAttributeMaxDynamicSharedMemorySize, SMEM_SZ);
        smem_set = 1;
    }

    prep_kernel<<<4224, 256>>>(z, c);
    gemm_kernel<<<NROWS / BM, 512, SMEM_SZ>>>(z, c, out);
}

// round 8
// speedup vs baseline: 1.3823x; 1.3823x over previous
#include <cuda_runtime.h>
#include <cuda_fp16.h>
#include <cstdint>

// ---------------------------------------------------------------------------
// Problem constants
// ---------------------------------------------------------------------------
#define NROWS 32768            // 64*512
#define KC    1024             // num centers
#define DDIM  256              // latent dim
#define BM    128              // CTA rows; CTA owns ALL 1024 output cols
#define BN    128              // column block per GEMM pass
#define NCB   (KC / BN)        // 8 column blocks
#define KCHUNK 64              // fp16 K-chunk: 64 halfs = 128B rows
#define NKC   (DDIM / KCHUNK)  // 4 K-chunks per column block
#define NJ    (NCB * NKC)      // 32 flat (cb,k) iterations
#define NSTG  4                // cp.async pipeline stages

#define A_STAGE (BM * KCHUNK * 2)      // 16384
#define B_STAGE (BN * KCHUNK * 2)      // 16384
#define SMEM_SZ (NSTG * (A_STAGE + B_STAGE))   // 131072

// ---------------------------------------------------------------------------
// Device-global scratch
// ---------------------------------------------------------------------------
__device__ __half g_zh[(size_t)NROWS * DDIM];   // fp16 z   (16 MB)
__device__ __half g_ch[(size_t)KC * DDIM];      // fp16 c   (0.5 MB)
__device__ float  g_zsq[NROWS];
__device__ float  g_csq[KC];

// ---------------------------------------------------------------------------
// helpers (sm_80-era PTX only — plain sm_100 target)
// ---------------------------------------------------------------------------
__device__ __forceinline__ uint32_t smem_u32(const void* p) {
    uint32_t a;
    asm("{ .reg .u64 t; cvta.to.shared.u64 t, %1; cvt.u32.u64 %0, t; }"
        : "=r"(a) : "l"(p));
    return a;
}
__device__ __forceinline__ void cpasync16(uint32_t dst, const void* src) {
    asm volatile("cp.async.cg.shared.global [%0], [%1], 16;"
                 :: "r"(dst), "l"(src));
}
__device__ __forceinline__ void ldsm4(uint32_t addr, uint32_t* d) {
    asm volatile("ldmatrix.sync.aligned.m8n8.x4.shared.b16 {%0,%1,%2,%3}, [%4];"
                 : "=r"(d[0]), "=r"(d[1]), "=r"(d[2]), "=r"(d[3])
                 : "r"(addr));
}
__device__ __forceinline__ void mma_f16(float* c, const uint32_t* a,
                                        uint32_t b0, uint32_t b1) {
    asm volatile(
        "mma.sync.aligned.m16n8k16.row.col.f32.f16.f16.f32 "
        "{%0,%1,%2,%3}, {%4,%5,%6,%7}, {%8,%9}, {%0,%1,%2,%3};"
        : "+f"(c[0]), "+f"(c[1]), "+f"(c[2]), "+f"(c[3])
        : "r"(a[0]), "r"(a[1]), "r"(a[2]), "r"(a[3]), "r"(b0), "r"(b1));
}

// ---------------------------------------------------------------------------
// Kernel 1: prep — squared row norms + fp16 conversion
// one warp per row
// ---------------------------------------------------------------------------
__global__ void prep_kernel(const float* __restrict__ z,
                            const float* __restrict__ c) {
    int gw   = (blockIdx.x * blockDim.x + threadIdx.x) >> 5;
    int lane = threadIdx.x & 31;
    if (gw >= NROWS + KC) return;

    const float* src;
    __half*      dst;
    if (gw < NROWS) { src = z + (size_t)gw * DDIM;           dst = g_zh + (size_t)gw * DDIM; }
    else            { src = c + (size_t)(gw - NROWS) * DDIM; dst = g_ch + (size_t)(gw - NROWS) * DDIM; }

    const float4* s4 = (const float4*)src;
    uint2*        d2 = (uint2*)dst;            // 4 fp16 = 8B per float4
    float s = 0.0f;
    #pragma unroll
    for (int i = 0; i < 2; i++) {
        float4 v = s4[lane + 32 * i];
        s += v.x * v.x + v.y * v.y + v.z * v.z + v.w * v.w;
        __half2 lo = __floats2half2_rn(v.x, v.y);
        __half2 hi = __floats2half2_rn(v.z, v.w);
        uint2 o;
        o.x = *(uint32_t*)&lo;
        o.y = *(uint32_t*)&hi;
        d2[lane + 32 * i] = o;
    }
    #pragma unroll
    for (int o = 16; o > 0; o >>= 1) s += __shfl_down_sync(0xffffffffu, s, o);
    if (lane == 0) {
        if (gw < NROWS) g_zsq[gw] = s;
        else            g_csq[gw - NROWS] = s;
    }
}

// ---------------------------------------------------------------------------
// Kernel 2: full-row fused FP16 GEMM + Student-t + in-CTA normalization
// grid = 256 CTAs, 512 threads (16 warps: 4M x 4N), warp tile 32x32
// 4-stage cp.async pipeline, single barrier per K-chunk
// ---------------------------------------------------------------------------
__global__ void __launch_bounds__(512, 1)
gemm_kernel(float* __restrict__ out) {
    extern __shared__ __align__(16) char smem[];
    uint32_t sb = smem_u32(smem);
    const uint32_t A0 = sb;
    const uint32_t B0 = sb + NSTG * A_STAGE;

    int tid  = threadIdx.x;
    int wid  = tid >> 5;
    int lane = tid & 31;
    int gr0  = blockIdx.x * BM;
    int wm   = (wid & 3) * 32;          // warp M offset (4 warps along M)
    int wn   = (wid >> 2) * 32;         // warp N offset (4 warps along N)
    int wnid = wid >> 2;

    // ---- chunk loader: j -> (cb = j>>2, k = j&3), stage j&3 ----
    // rows: 128 x 128B (64 fp16); 8 x 16B chunks per row, XOR-swizzled
    auto load_chunk = [&](int j) {
        int cb = j >> 2, k = j & 3;
        uint32_t ab = A0 + (j & 3) * A_STAGE;
        uint32_t bb = B0 + (j & 3) * B_STAGE;
        const __half* gA = g_zh + (size_t)gr0 * DDIM + k * KCHUNK;
        const __half* gB = g_ch + (size_t)(cb * BN) * DDIM + k * KCHUNK;
        #pragma unroll
        for (int u = 0; u < 2; u++) {            // 1024 x 16B / 512 threads
            int f = u * 512 + tid;
            int row = f >> 3, c4 = f & 7;
            cpasync16(ab + row * 128 + 16 * (c4 ^ (row & 7)),
                      gA + (size_t)row * DDIM + c4 * 8);
        }
        #pragma unroll
        for (int u = 0; u < 2; u++) {
            int f = u * 512 + tid;
            int row = f >> 3, c4 = f & 7;
            cpasync16(bb + row * 128 + 16 * (c4 ^ (row & 7)),
                      gB + (size_t)row * DDIM + c4 * 8);
        }
        asm volatile("cp.async.commit_group;");
    };
    load_chunk(0);
    load_chunk(1);
    load_chunk(2);

    // ---- ldmatrix address precompute (identical geometry to tf32 version) ----
    int g = lane >> 3, r = lane & 7;
    uint32_t aOff[2], aSw[2];
    #pragma unroll
    for (int ms = 0; ms < 2; ms++) {
        int row = wm + ms * 16 + (g & 1) * 8 + r;
        aOff[ms] = (uint32_t)row * 128;
        aSw[ms]  = (uint32_t)(row & 7);
    }
    uint32_t aDu = (uint32_t)(g >> 1);
    uint32_t bOff[2], bSw[2];
    #pragma unroll
    for (int nj = 0; nj < 2; nj++) {
        int row = wn + nj * 16 + (g >> 1) * 8 + r;
        bOff[nj] = (uint32_t)row * 128;
        bSw[nj]  = (uint32_t)(row & 7);
    }
    uint32_t bDu = (uint32_t)(g & 1);

    float acc[2][4][4];
    #pragma unroll
    for (int ms = 0; ms < 2; ms++)
        #pragma unroll
        for (int ns = 0; ns < 4; ns++)
            #pragma unroll
            for (int q = 0; q < 4; q++) acc[ms][ns][q] = 0.0f;

    int tig = lane & 3, gid = lane >> 2;
    float rs[2][2] = {{0.f, 0.f}, {0.f, 0.f}};

    // ---- flat mainloop: single barrier per chunk, 4-stage prefetch ----
    #pragma unroll 1
    for (int j = 0; j < NJ; j++) {
        asm volatile("cp.async.wait_group 2;");   // group j retired
        __syncthreads();

        // refill stage (j+3)&3 == (j-1)&3 (its compute finished pre-barrier)
        if (j + 3 < NJ) load_chunk(j + 3);
        else            asm volatile("cp.async.commit_group;");  // keep count

        uint32_t ab = A0 + (j & 3) * A_STAGE;
        uint32_t bb = B0 + (j & 3) * B_STAGE;
        #pragma unroll
        for (int kk = 0; kk < 4; kk++) {          // k16 per step; 64 per chunk
            uint32_t afr[2][4], bfr[2][4];
            #pragma unroll
            for (int ms = 0; ms < 2; ms++)
                ldsm4(ab + aOff[ms] + 16 * ((2 * kk + aDu) ^ aSw[ms]), afr[ms]);
            #pragma unroll
            for (int nj = 0; nj < 2; nj++)
                ldsm4(bb + bOff[nj] + 16 * ((2 * kk + bDu) ^ bSw[nj]), bfr[nj]);
            // bfr regs: r0 = n0-7/k0-7, r1 = n0-7/k8-15, r2 = n8-15/k0-7, r3 = n8-15/k8-15
            #pragma unroll
            for (int ms = 0; ms < 2; ms++)
                #pragma unroll
                for (int ns = 0; ns < 4; ns++)
                    mma_f16(acc[ms][ns], afr[ms],
                            bfr[ns >> 1][(ns & 1) * 2],
                            bfr[ns >> 1][(ns & 1) * 2 + 1]);
        }

        if ((j & 3) == 3) {
            // ---- epilogue for finished column block (overlaps prefetch) ----
            int cb = j >> 2;
            #pragma unroll
            for (int ms = 0; ms < 2; ms++) {
                int r0 = gr0 + wm + 16 * ms + gid;
                float zs0 = g_zsq[r0];
                float zs1 = g_zsq[r0 + 8];
                #pragma unroll
                for (int ns = 0; ns < 4; ns++) {
                    int col = cb * BN + wn + 8 * ns + 2 * tig;
                    float cs0 = __ldg(&g_csq[col]);
                    float cs1 = __ldg(&g_csq[col + 1]);
                    float d00 = fmaxf(fmaf(-2.0f, acc[ms][ns][0], zs0 + cs0), 0.0f);
                    float d01 = fmaxf(fmaf(-2.0f, acc[ms][ns][1], zs0 + cs1), 0.0f);
                    float d10 = fmaxf(fmaf(-2.0f, acc[ms][ns][2], zs1 + cs0), 0.0f);
                    float d11 = fmaxf(fmaf(-2.0f, acc[ms][ns][3], zs1 + cs1), 0.0f);
                    float s00, s01, s10, s11;
                    { float x = fmaf(d00, 0.1f, 1.0f); float y = rsqrtf(x);
                      float y2 = y*y, y4 = y2*y2, y8 = y4*y4; s00 = y8*y2*y; }
                    { float x = fmaf(d01, 0.1f, 1.0f); float y = rsqrtf(x);
                      float y2 = y*y, y4 = y2*y2, y8 = y4*y4; s01 = y8*y2*y; }
                    { float x = fmaf(d10, 0.1f, 1.0f); float y = rsqrtf(x);
                      float y2 = y*y, y4 = y2*y2, y8 = y4*y4; s10 = y8*y2*y; }
                    { float x = fmaf(d11, 0.1f, 1.0f); float y = rsqrtf(x);
                      float y2 = y*y, y4 = y2*y2, y8 = y4*y4; s11 = y8*y2*y; }
                    rs[ms][0] += s00 + s01;
                    rs[ms][1] += s10 + s11;
                    *(float2*)(out + (size_t)r0 * KC + col)       = make_float2(s00, s01);
                    *(float2*)(out + (size_t)(r0 + 8) * KC + col) = make_float2(s10, s11);
                    acc[ms][ns][0] = 0.f; acc[ms][ns][1] = 0.f;
                    acc[ms][ns][2] = 0.f; acc[ms][ns][3] = 0.f;
                }
            }
        }
    }

    // ---- row-sum reduction: quad -> smem -> inv per row ----
    #pragma unroll
    for (int ms = 0; ms < 2; ms++)
        #pragma unroll
        for (int h = 0; h < 2; h++) {
            float v = rs[ms][h];
            v += __shfl_xor_sync(0xffffffffu, v, 1);
            v += __shfl_xor_sync(0xffffffffu, v, 2);
            rs[ms][h] = v;
        }
    __syncthreads();                  // tiles dead; reuse smem
    float* red = (float*)smem;        // [128 rows][4 warp_n]
    float* inv = red + 512;
    if (tig == 0) {
        #pragma unroll
        for (int ms = 0; ms < 2; ms++)
            #pragma unroll
            for (int h = 0; h < 2; h++)
                red[(wm + 16 * ms + 8 * h + gid) * 4 + wnid] = rs[ms][h];
    }
    __syncthreads();
    if (tid < BM)
        inv[tid] = 1.0f / (red[tid * 4] + red[tid * 4 + 1]
                         + red[tid * 4 + 2] + red[tid * 4 + 3]);
    __syncthreads();

    // ---- in-CTA normalization pass over own 512KB tile (L2-hot) ----
    float4* o4 = (float4*)out + (size_t)gr0 * (KC / 4);
    #pragma unroll 4
    for (int u = 0; u < 64; u++) {
        int idx = u * 512 + tid;
        float iv = inv[idx >> 8];          // 256 float4 per row
        float4 v = o4[idx];
        v.x *= iv; v.y *= iv; v.z *= iv; v.w *= iv;
        o4[idx] = v;
    }
}

// ---------------------------------------------------------------------------
extern "C" void kernel_launch(void* const* d_in, const int* in_sizes, int n_in,
                              void* d_out, int out_size) {
    const float* z = (const float*)d_in[0];
    const float* c = (const float*)d_in[1];
    if (in_sizes[0] == KC * DDIM) {          // defensive: metadata order
        const float* t = z; z = c; c = t;
    }
    float* out = (float*)d_out;

    static int smem_set = 0;
    if (!smem_set) {
        cudaFuncSetAttribute(gemm_kernel,
                             cudaFuncAttributeMaxDynamicSharedMemorySize, SMEM_SZ);
        smem_set = 1;
    }

    prep_kernel<<<4224, 256>>>(z, c);
    gemm_kernel<<<NROWS / BM, 512, SMEM_SZ>>>(out);
}

// round 9
// speedup vs baseline: 1.5714x; 1.1368x over previous
#include <cuda_runtime.h>
#include <cuda_fp16.h>
#include <cstdint>

// ---------------------------------------------------------------------------
// Problem constants
// ---------------------------------------------------------------------------
#define NROWS 32768            // 64*512
#define KC    1024             // num centers
#define DDIM  256              // latent dim
#define BM    128              // CTA rows; CTA owns ALL 1024 output cols
#define BN    128              // column block
#define NCB   (KC / BN)        // 8 column blocks

// smem layout: A resident (4 slabs x 128rows x 64 fp16), B 2 stages same shape
#define SLAB  16384            // 128 rows * 64 fp16 * 2B = 128B rows
#define A_BYTES (4 * SLAB)     // 65536
#define B_STAGE (4 * SLAB)     // 65536
#define SMEM_SZ (A_BYTES + 2 * B_STAGE)   // 196608

// ---------------------------------------------------------------------------
// Device-global scratch
// ---------------------------------------------------------------------------
__device__ __half g_zh[(size_t)NROWS * DDIM];   // fp16 z   (16 MB)
__device__ __half g_ch[(size_t)KC * DDIM];      // fp16 c   (0.5 MB)
__device__ float  g_zsq[NROWS];
__device__ float  g_csq[KC];

// ---------------------------------------------------------------------------
// helpers (sm_80-era PTX only — plain sm_100 target)
// ---------------------------------------------------------------------------
__device__ __forceinline__ uint32_t smem_u32(const void* p) {
    uint32_t a;
    asm("{ .reg .u64 t; cvta.to.shared.u64 t, %1; cvt.u32.u64 %0, t; }"
        : "=r"(a) : "l"(p));
    return a;
}
__device__ __forceinline__ void cpasync16(uint32_t dst, const void* src) {
    asm volatile("cp.async.cg.shared.global [%0], [%1], 16;"
                 :: "r"(dst), "l"(src));
}
__device__ __forceinline__ void ldsm4(uint32_t addr, uint32_t* d) {
    asm volatile("ldmatrix.sync.aligned.m8n8.x4.shared.b16 {%0,%1,%2,%3}, [%4];"
                 : "=r"(d[0]), "=r"(d[1]), "=r"(d[2]), "=r"(d[3])
                 : "r"(addr));
}
__device__ __forceinline__ void mma_f16(float* c, const uint32_t* a,
                                        uint32_t b0, uint32_t b1) {
    asm volatile(
        "mma.sync.aligned.m16n8k16.row.col.f32.f16.f16.f32 "
        "{%0,%1,%2,%3}, {%4,%5,%6,%7}, {%8,%9}, {%0,%1,%2,%3};"
        : "+f"(c[0]), "+f"(c[1]), "+f"(c[2]), "+f"(c[3])
        : "r"(a[0]), "r"(a[1]), "r"(a[2]), "r"(a[3]), "r"(b0), "r"(b1));
}

// ---------------------------------------------------------------------------
// Kernel 1: prep — squared row norms + fp16 conversion (one warp per row)
// ---------------------------------------------------------------------------
__global__ void prep_kernel(const float* __restrict__ z,
                            const float* __restrict__ c) {
    int gw   = (blockIdx.x * blockDim.x + threadIdx.x) >> 5;
    int lane = threadIdx.x & 31;
    if (gw >= NROWS + KC) return;

    const float* src;
    __half*      dst;
    if (gw < NROWS) { src = z + (size_t)gw * DDIM;           dst = g_zh + (size_t)gw * DDIM; }
    else            { src = c + (size_t)(gw - NROWS) * DDIM; dst = g_ch + (size_t)(gw - NROWS) * DDIM; }

    const float4* s4 = (const float4*)src;
    uint2*        d2 = (uint2*)dst;
    float s = 0.0f;
    #pragma unroll
    for (int i = 0; i < 2; i++) {
        float4 v = s4[lane + 32 * i];
        s += v.x * v.x + v.y * v.y + v.z * v.z + v.w * v.w;
        __half2 lo = __floats2half2_rn(v.x, v.y);
        __half2 hi = __floats2half2_rn(v.z, v.w);
        uint2 o;
        o.x = *(uint32_t*)&lo;
        o.y = *(uint32_t*)&hi;
        d2[lane + 32 * i] = o;
    }
    #pragma unroll
    for (int o = 16; o > 0; o >>= 1) s += __shfl_down_sync(0xffffffffu, s, o);
    if (lane == 0) {
        if (gw < NROWS) g_zsq[gw] = s;
        else            g_csq[gw - NROWS] = s;
    }
}

// ---------------------------------------------------------------------------
// Kernel 2: resident-A FP16 GEMM + Student-t + in-CTA normalization
// grid = 256 CTAs, 512 threads (16 warps: 4M x 4N), warp tile 32x32
// mainloop: 8 column blocks; B double-buffered; 2 barriers per block
// ---------------------------------------------------------------------------
__global__ void __launch_bounds__(512, 1)
gemm_kernel(float* __restrict__ out) {
    extern __shared__ __align__(16) char smem[];
    uint32_t sb = smem_u32(smem);
    const uint32_t A0 = sb;
    const uint32_t B0 = sb + A_BYTES;

    int tid  = threadIdx.x;
    int wid  = tid >> 5;
    int lane = tid & 31;
    int gr0  = blockIdx.x * BM;
    int wm   = (wid & 3) * 32;          // warp M offset (4 warps along M)
    int wn   = (wid >> 2) * 32;         // warp N offset (4 warps along N)
    int wnid = wid >> 2;

    // ---- A loader (once): 4096 x 16B; slab s = dims [s*64, s*64+64) ----
    {
        #pragma unroll
        for (int u = 0; u < 8; u++) {
            int f = u * 512 + tid;
            int slab = f >> 10, rr = (f >> 3) & 127, c4 = f & 7;
            cpasync16(A0 + slab * SLAB + rr * 128 + 16 * (c4 ^ (rr & 7)),
                      g_zh + (size_t)(gr0 + rr) * DDIM + slab * 64 + c4 * 8);
        }
        asm volatile("cp.async.commit_group;");
    }

    // ---- B loader: col block cb -> stage cb&1 (4 slabs) ----
    auto load_B = [&](int cb) {
        uint32_t bb = B0 + (cb & 1) * B_STAGE;
        const __half* gB = g_ch + (size_t)(cb * BN) * DDIM;
        #pragma unroll
        for (int u = 0; u < 8; u++) {
            int f = u * 512 + tid;
            int slab = f >> 10, rr = (f >> 3) & 127, c4 = f & 7;
            cpasync16(bb + slab * SLAB + rr * 128 + 16 * (c4 ^ (rr & 7)),
                      gB + (size_t)rr * DDIM + slab * 64 + c4 * 8);
        }
        asm volatile("cp.async.commit_group;");
    };
    load_B(0);
    load_B(1);

    // ---- ldmatrix address precompute ----
    int g = lane >> 3, r = lane & 7;
    uint32_t aOff[2], aSw[2];
    #pragma unroll
    for (int ms = 0; ms < 2; ms++) {
        int row = wm + ms * 16 + (g & 1) * 8 + r;
        aOff[ms] = (uint32_t)row * 128;
        aSw[ms]  = (uint32_t)(row & 7);
    }
    uint32_t aDu = (uint32_t)(g >> 1);
    uint32_t bOff[2], bSw[2];
    #pragma unroll
    for (int nj = 0; nj < 2; nj++) {
        int row = wn + nj * 16 + (g >> 1) * 8 + r;
        bOff[nj] = (uint32_t)row * 128;
        bSw[nj]  = (uint32_t)(row & 7);
    }
    uint32_t bDu = (uint32_t)(g & 1);

    float acc[2][4][4];
    #pragma unroll
    for (int ms = 0; ms < 2; ms++)
        #pragma unroll
        for (int ns = 0; ns < 4; ns++)
            #pragma unroll
            for (int q = 0; q < 4; q++) acc[ms][ns][q] = 0.0f;

    int tig = lane & 3, gid = lane >> 2;
    float rs[2][2] = {{0.f, 0.f}, {0.f, 0.f}};

    // ---- mainloop over 8 column blocks ----
    #pragma unroll 1
    for (int cb = 0; cb < NCB; cb++) {
        asm volatile("cp.async.wait_group 1;");    // B(cb) (and A) landed
        __syncthreads();

        uint32_t bstage = B0 + (cb & 1) * B_STAGE;
        // unbroken compute run: 4 slabs x 4 k16 steps = 64 LDSM + 128 HMMA
        #pragma unroll
        for (int slab = 0; slab < 4; slab++) {
            uint32_t ab = A0 + slab * SLAB;
            uint32_t bb = bstage + slab * SLAB;
            #pragma unroll
            for (int kk = 0; kk < 4; kk++) {
                uint32_t afr[2][4], bfr[2][4];
                #pragma unroll
                for (int ms = 0; ms < 2; ms++)
                    ldsm4(ab + aOff[ms] + 16 * ((2 * kk + aDu) ^ aSw[ms]), afr[ms]);
                #pragma unroll
                for (int nj = 0; nj < 2; nj++)
                    ldsm4(bb + bOff[nj] + 16 * ((2 * kk + bDu) ^ bSw[nj]), bfr[nj]);
                #pragma unroll
                for (int ms = 0; ms < 2; ms++)
                    #pragma unroll
                    for (int ns = 0; ns < 4; ns++)
                        mma_f16(acc[ms][ns], afr[ms],
                                bfr[ns >> 1][(ns & 1) * 2],
                                bfr[ns >> 1][(ns & 1) * 2 + 1]);
            }
        }
        __syncthreads();                           // stage cb&1 free

        if (cb + 2 < NCB) load_B(cb + 2);          // refill freed stage
        else              asm volatile("cp.async.commit_group;");

        // ---- epilogue for this column block (overlaps B load) ----
        #pragma unroll
        for (int ms = 0; ms < 2; ms++) {
            int r0 = gr0 + wm + 16 * ms + gid;
            float zs0 = g_zsq[r0];
            float zs1 = g_zsq[r0 + 8];
            #pragma unroll
            for (int ns = 0; ns < 4; ns++) {
                int col = cb * BN + wn + 8 * ns + 2 * tig;
                float cs0 = __ldg(&g_csq[col]);
                float cs1 = __ldg(&g_csq[col + 1]);
                float d00 = fmaxf(fmaf(-2.0f, acc[ms][ns][0], zs0 + cs0), 0.0f);
                float d01 = fmaxf(fmaf(-2.0f, acc[ms][ns][1], zs0 + cs1), 0.0f);
                float d10 = fmaxf(fmaf(-2.0f, acc[ms][ns][2], zs1 + cs0), 0.0f);
                float d11 = fmaxf(fmaf(-2.0f, acc[ms][ns][3], zs1 + cs1), 0.0f);
                float s00, s01, s10, s11;
                { float x = fmaf(d00, 0.1f, 1.0f); float y = rsqrtf(x);
                  float y2 = y*y, y4 = y2*y2, y8 = y4*y4; s00 = y8*y2*y; }
                { float x = fmaf(d01, 0.1f, 1.0f); float y = rsqrtf(x);
                  float y2 = y*y, y4 = y2*y2, y8 = y4*y4; s01 = y8*y2*y; }
                { float x = fmaf(d10, 0.1f, 1.0f); float y = rsqrtf(x);
                  float y2 = y*y, y4 = y2*y2, y8 = y4*y4; s10 = y8*y2*y; }
                { float x = fmaf(d11, 0.1f, 1.0f); float y = rsqrtf(x);
                  float y2 = y*y, y4 = y2*y2, y8 = y4*y4; s11 = y8*y2*y; }
                rs[ms][0] += s00 + s01;
                rs[ms][1] += s10 + s11;
                *(float2*)(out + (size_t)r0 * KC + col)       = make_float2(s00, s01);
                *(float2*)(out + (size_t)(r0 + 8) * KC + col) = make_float2(s10, s11);
                acc[ms][ns][0] = 0.f; acc[ms][ns][1] = 0.f;
                acc[ms][ns][2] = 0.f; acc[ms][ns][3] = 0.f;
            }
        }
    }

    // ---- row-sum reduction: quad -> smem -> inv per row ----
    #pragma unroll
    for (int ms = 0; ms < 2; ms++)
        #pragma unroll
        for (int h = 0; h < 2; h++) {
            float v = rs[ms][h];
            v += __shfl_xor_sync(0xffffffffu, v, 1);
            v += __shfl_xor_sync(0xffffffffu, v, 2);
            rs[ms][h] = v;
        }
    __syncthreads();                  // tiles dead; reuse smem
    float* red = (float*)smem;        // [128 rows][4 warp_n]
    float* inv = red + 512;
    if (tig == 0) {
        #pragma unroll
        for (int ms = 0; ms < 2; ms++)
            #pragma unroll
            for (int h = 0; h < 2; h++)
                red[(wm + 16 * ms + 8 * h + gid) * 4 + wnid] = rs[ms][h];
    }
    __syncthreads();
    if (tid < BM)
        inv[tid] = 1.0f / (red[tid * 4] + red[tid * 4 + 1]
                         + red[tid * 4 + 2] + red[tid * 4 + 3]);
    __syncthreads();

    // ---- in-CTA normalization pass over own 512KB tile (L2-hot) ----
    float4* o4 = (float4*)out + (size_t)gr0 * (KC / 4);
    #pragma unroll 4
    for (int u = 0; u < 64; u++) {
        int idx = u * 512 + tid;
        float iv = inv[idx >> 8];          // 256 float4 per row
        float4 v = o4[idx];
        v.x *= iv; v.y *= iv; v.z *= iv; v.w *= iv;
        o4[idx] = v;
    }
}

// ---------------------------------------------------------------------------
extern "C" void kernel_launch(void* const* d_in, const int* in_sizes, int n_in,
                              void* d_out, int out_size) {
    const float* z = (const float*)d_in[0];
    const float* c = (const float*)d_in[1];
    if (in_sizes[0] == KC * DDIM) {          // defensive: metadata order
        const float* t = z; z = c; c = t;
    }
    float* out = (float*)d_out;

    static int smem_set = 0;
    if (!smem_set) {
        cudaFuncSetAttribute(gemm_kernel,
                             cudaFuncAttributeMaxDynamicSharedMemorySize, SMEM_SZ);
        smem_set = 1;
    }

    prep_kernel<<<4224, 256>>>(z, c);
    gemm_kernel<<<NROWS / BM, 512, SMEM_SZ>>>(out);
}